// round 3
// baseline (speedup 1.0000x reference)
#include <cuda_runtime.h>
#include <math.h>

// Problem constants
#define V_  50257
#define E_  256
#define H_  512
#define B_  64
#define L_  64
#define SOS_ 2

#define GR_     2048   // virtual gate rows: r(512) | z(512) | i_n(512) | h_n(512)
#define KSPLIT_ 4
#define KTOT_   768    // E + H concatenated
#define KPER_   (KTOT_ / KSPLIT_)   // 192

// ---------------- device scratch (no allocations allowed) ----------------
__device__ float g_h[B_ * H_];                         // current hidden state (updated in place each step)
__device__ float g_part[KSPLIT_][B_ * GR_];            // split-K partial gate sums
__device__ unsigned long long g_amax[L_][B_];          // per-step packed argmax accumulators

// ---------------- init: copy h0, zero argmax accumulators ----------------
__global__ void k_init(const float* __restrict__ h0) {
    int stride = gridDim.x * blockDim.x;
    int i = blockIdx.x * blockDim.x + threadIdx.x;
    for (int j = i; j < B_ * H_; j += stride) g_h[j] = h0[j];
    unsigned long long* am = &g_amax[0][0];
    for (int j = i; j < L_ * B_; j += stride) am[j] = 0ull;
}

// ---------------- gate GEMM: [64 x 2048] = xh[64 x 768] @ Wgate^T, split-K=4 ----------------
// Row regions of the virtual gate matrix:
//   [0,1024)    : r,z rows -> W_ih[r][k] for k<E, W_hh[r][k-E] for k>=E   (gi+gh summed)
//   [1024,1536) : i_n rows -> W_ih[r][k] for k<E, zero for k>=E
//   [1536,2048) : h_n rows -> zero for k<E, W_hh[r-512][k-E] for k>=E
__global__ __launch_bounds__(256) void k_gates_gemm(
    int t,
    const float* __restrict__ emb,
    const float* __restrict__ W_ih,
    const float* __restrict__ W_hh)
{
    int rt = blockIdx.x / KSPLIT_;      // row-tile 0..31
    int ks = blockIdx.x % KSPLIT_;      // k-split 0..3
    int r0 = rt * 64;
    int kbase = ks * KPER_;
    int region = (r0 < 1024) ? 0 : (r0 < 1536 ? 1 : 2);

    __shared__ float As[32][68];
    __shared__ float Bs[32][68];
    __shared__ int   s_tok[B_];

    int tid = threadIdx.x;
    if (tid < B_) {
        int tok;
        if (t == 0) tok = SOS_;
        else {
            unsigned long long key = g_amax[t - 1][tid];
            tok = (int)(0xFFFFFFFFu - (unsigned)(key & 0xFFFFFFFFull));
        }
        s_tok[tid] = tok;
    }
    __syncthreads();

    int tx = tid & 15, ty = tid >> 4;
    float acc[4][4] = {};

    for (int kc = 0; kc < KPER_; kc += 32) {
        int k0 = kbase + kc;
        // uniform-per-block skip of all-zero chunks
        if (region == 1 && k0 >= E_) continue;          // i_n: only k < E contributes
        if (region == 2 && k0 + 32 <= E_) continue;     // h_n: only k >= E contributes

        __syncthreads();
        // load A tile: As[kk][bb] = xh[b][k0+kk]  (k-major, transposed on store)
        #pragma unroll
        for (int u = 0; u < 2; u++) {
            int idx = tid * 2 + u;
            int b = idx >> 3, q = idx & 7;
            int k = k0 + q * 4;
            float4 v;
            if (k < E_) v = *(const float4*)(emb + (size_t)s_tok[b] * E_ + k);
            else        v = *(const float4*)(g_h + b * H_ + (k - E_));
            As[q * 4 + 0][b] = v.x; As[q * 4 + 1][b] = v.y;
            As[q * 4 + 2][b] = v.z; As[q * 4 + 3][b] = v.w;
        }
        // load B tile: Bs[kk][rr] = Wgate[r0+rr][k0+kk]
        #pragma unroll
        for (int u = 0; u < 2; u++) {
            int idx = tid * 2 + u;
            int rr = idx >> 3, q = idx & 7;
            int k = k0 + q * 4;
            int r = r0 + rr;
            float4 v;
            if (region == 0) {
                if (k < E_) v = *(const float4*)(W_ih + (size_t)r * E_ + k);
                else        v = *(const float4*)(W_hh + (size_t)r * H_ + (k - E_));
            } else if (region == 1) {
                v = *(const float4*)(W_ih + (size_t)r * E_ + k);            // k < E guaranteed
            } else {
                v = *(const float4*)(W_hh + (size_t)(r - 512) * H_ + (k - E_)); // k >= E guaranteed
            }
            Bs[q * 4 + 0][rr] = v.x; Bs[q * 4 + 1][rr] = v.y;
            Bs[q * 4 + 2][rr] = v.z; Bs[q * 4 + 3][rr] = v.w;
        }
        __syncthreads();

        #pragma unroll
        for (int k = 0; k < 32; k++) {
            float a[4], w[4];
            *(float4*)a = *(const float4*)&As[k][ty * 4];
            *(float4*)w = *(const float4*)&Bs[k][tx * 4];
            #pragma unroll
            for (int i = 0; i < 4; i++)
                #pragma unroll
                for (int j = 0; j < 4; j++)
                    acc[i][j] = fmaf(a[i], w[j], acc[i][j]);
        }
    }

    float* outp = &g_part[ks][0];
    #pragma unroll
    for (int i = 0; i < 4; i++) {
        int b = ty * 4 + i;
        #pragma unroll
        for (int j = 0; j < 4; j++) {
            int r = r0 + tx * 4 + j;
            outp[b * GR_ + r] = acc[i][j];
        }
    }
}

// ---------------- gate nonlinearity + hidden update (in place) ----------------
__global__ __launch_bounds__(256) void k_gates_elem(
    const float* __restrict__ b_ih, const float* __restrict__ b_hh)
{
    int i = blockIdx.x * blockDim.x + threadIdx.x;   // 0 .. B*H-1
    if (i >= B_ * H_) return;
    int b = i >> 9;          // / 512
    int j = i & 511;

    float sr = 0.f, sz = 0.f, in_ = 0.f, hn = 0.f;
    #pragma unroll
    for (int s = 0; s < KSPLIT_; s++) {
        const float* row = &g_part[s][b * GR_];
        sr  += row[j];
        sz  += row[512 + j];
        in_ += row[1024 + j];
        hn  += row[1536 + j];
    }
    sr  += b_ih[j] + b_hh[j];
    sz  += b_ih[512 + j] + b_hh[512 + j];
    in_ += b_ih[1024 + j];
    hn  += b_hh[1024 + j];

    float r = 1.f / (1.f + expf(-sr));
    float z = 1.f / (1.f + expf(-sz));
    float n = tanhf(in_ + r * hn);
    g_h[i] = (1.f - z) * n + z * g_h[i];
}

// ---------------- classifier logits + fused argmax ----------------
__global__ __launch_bounds__(256) void k_logits(
    int t,
    const float* __restrict__ Wc,
    const float* __restrict__ bc,
    float* __restrict__ out)
{
    int v0 = blockIdx.x * 64;
    __shared__ float As[32][68];
    __shared__ float Bs[32][68];

    int tid = threadIdx.x;
    int tx = tid & 15, ty = tid >> 4;
    float acc[4][4] = {};

    for (int k0 = 0; k0 < H_; k0 += 32) {
        __syncthreads();
        #pragma unroll
        for (int u = 0; u < 2; u++) {
            int idx = tid * 2 + u;
            int b = idx >> 3, q = idx & 7;
            int k = k0 + q * 4;
            float4 v = *(const float4*)(g_h + b * H_ + k);
            As[q * 4 + 0][b] = v.x; As[q * 4 + 1][b] = v.y;
            As[q * 4 + 2][b] = v.z; As[q * 4 + 3][b] = v.w;
        }
        #pragma unroll
        for (int u = 0; u < 2; u++) {
            int idx = tid * 2 + u;
            int rr = idx >> 3, q = idx & 7;
            int k = k0 + q * 4;
            int vg = v0 + rr;
            float4 w;
            if (vg < V_) w = *(const float4*)(Wc + (size_t)vg * H_ + k);
            else         w = make_float4(0.f, 0.f, 0.f, 0.f);
            Bs[q * 4 + 0][rr] = w.x; Bs[q * 4 + 1][rr] = w.y;
            Bs[q * 4 + 2][rr] = w.z; Bs[q * 4 + 3][rr] = w.w;
        }
        __syncthreads();

        #pragma unroll
        for (int k = 0; k < 32; k++) {
            float a[4], w[4];
            *(float4*)a = *(const float4*)&As[k][ty * 4];
            *(float4*)w = *(const float4*)&Bs[k][tx * 4];
            #pragma unroll
            for (int i = 0; i < 4; i++)
                #pragma unroll
                for (int j = 0; j < 4; j++)
                    acc[i][j] = fmaf(a[i], w[j], acc[i][j]);
        }
    }

    // bias + output store + packed-key argmax candidates
    float* outt = out + (size_t)t * B_ * V_;
    unsigned long long best[4] = {0ull, 0ull, 0ull, 0ull};
    #pragma unroll
    for (int j = 0; j < 4; j++) {
        int vg = v0 + tx * 4 + j;
        if (vg >= V_) continue;
        float bcv = bc[vg];
        #pragma unroll
        for (int i = 0; i < 4; i++) {
            int b = ty * 4 + i;
            float l = acc[i][j] + bcv;
            outt[(size_t)b * V_ + vg] = l;
            unsigned u = __float_as_uint(l);
            u = (u & 0x80000000u) ? ~u : (u | 0x80000000u);  // orderable float
            unsigned long long key =
                ((unsigned long long)u << 32) | (unsigned long long)(0xFFFFFFFFu - (unsigned)vg);
            if (key > best[i]) best[i] = key;                // ties -> lowest index wins
        }
    }
    // reduce across the 16 v-lanes sharing the same 4 batch rows
    #pragma unroll
    for (int off = 8; off > 0; off >>= 1) {
        #pragma unroll
        for (int i = 0; i < 4; i++) {
            unsigned long long o = __shfl_down_sync(0xFFFFFFFFu, best[i], off, 16);
            if (o > best[i]) best[i] = o;
        }
    }
    if (tx == 0) {
        #pragma unroll
        for (int i = 0; i < 4; i++)
            atomicMax(&g_amax[t][ty * 4 + i], best[i]);
    }
}

// ---------------- launch ----------------
extern "C" void kernel_launch(void* const* d_in, const int* in_sizes, int n_in,
                              void* d_out, int out_size) {
    const float* h0   = (const float*)d_in[0];
    const float* emb  = (const float*)d_in[1];
    const float* W_ih = (const float*)d_in[2];
    const float* W_hh = (const float*)d_in[3];
    const float* b_ih = (const float*)d_in[4];
    const float* b_hh = (const float*)d_in[5];
    const float* Wc   = (const float*)d_in[6];
    const float* bc   = (const float*)d_in[7];
    float* out = (float*)d_out;

    k_init<<<32, 256>>>(h0);
    int gemm_blocks   = (GR_ / 64) * KSPLIT_;       // 128
    int elem_blocks   = (B_ * H_) / 256;            // 128
    int logits_blocks = (V_ + 63) / 64;             // 786
    for (int t = 0; t < L_; t++) {
        k_gates_gemm<<<gemm_blocks, 256>>>(t, emb, W_ih, W_hh);
        k_gates_elem<<<elem_blocks, 256>>>(b_ih, b_hh);
        k_logits<<<logits_blocks, 256>>>(t, Wc, bc, out);
    }
}

// round 4
// speedup vs baseline: 1.1780x; 1.1780x over previous
#include <cuda_runtime.h>
#include <math.h>

// Problem constants
#define V_  50257
#define E_  256
#define H_  512
#define B_  64
#define L_  64
#define SOS_ 2

#define GR_     2048   // virtual gate rows: r(512) | z(512) | i_n(512) | h_n(512)
#define KSPLIT_ 4
#define KTOT_   768    // E + H concatenated
#define KPER_   (KTOT_ / KSPLIT_)   // 192

// ---------------- device scratch (no allocations allowed) ----------------
__device__ float g_h[B_ * H_];                         // current hidden state
__device__ float g_part[KSPLIT_][B_ * GR_];            // split-K partial gate sums
__device__ unsigned long long g_amax[L_][B_];          // per-step packed argmax accumulators

// packed dual-FMA: (d.lo,d.hi) = (a.lo*b.lo+c.lo, a.hi*b.hi+c.hi)
__device__ __forceinline__ unsigned long long ffma2(
    unsigned long long a, unsigned long long b, unsigned long long c)
{
    unsigned long long d;
    asm("fma.rn.f32x2 %0, %1, %2, %3;" : "=l"(d) : "l"(a), "l"(b), "l"(c));
    return d;
}

// ---------------- init: copy h0, zero argmax accumulators ----------------
__global__ void k_init(const float* __restrict__ h0) {
    int stride = gridDim.x * blockDim.x;
    int i = blockIdx.x * blockDim.x + threadIdx.x;
    for (int j = i; j < B_ * H_; j += stride) g_h[j] = h0[j];
    unsigned long long* am = &g_amax[0][0];
    for (int j = i; j < L_ * B_; j += stride) am[j] = 0ull;
}

// ---------------- gate GEMM: [64 x 2048] = xh[64 x 768] @ Wgate^T, split-K=4 ----------------
__global__ __launch_bounds__(256) void k_gates_gemm(
    int t,
    const float* __restrict__ emb,
    const float* __restrict__ W_ih,
    const float* __restrict__ W_hh)
{
    int rt = blockIdx.x / KSPLIT_;
    int ks = blockIdx.x % KSPLIT_;
    int r0 = rt * 64;
    int kbase = ks * KPER_;
    int region = (r0 < 1024) ? 0 : (r0 < 1536 ? 1 : 2);

    __shared__ float As[32][68];
    __shared__ float Bs[32][68];
    __shared__ int   s_tok[B_];

    int tid = threadIdx.x;
    if (tid < B_) {
        int tok;
        if (t == 0) tok = SOS_;
        else {
            unsigned long long key = g_amax[t - 1][tid];
            tok = (int)(0xFFFFFFFFu - (unsigned)(key & 0xFFFFFFFFull));
        }
        s_tok[tid] = tok;
    }
    __syncthreads();

    int tx = tid & 15, ty = tid >> 4;
    float acc[4][4] = {};

    for (int kc = 0; kc < KPER_; kc += 32) {
        int k0 = kbase + kc;
        if (region == 1 && k0 >= E_) continue;
        if (region == 2 && k0 + 32 <= E_) continue;

        __syncthreads();
        #pragma unroll
        for (int u = 0; u < 2; u++) {
            int idx = tid * 2 + u;
            int b = idx >> 3, q = idx & 7;
            int k = k0 + q * 4;
            float4 v;
            if (k < E_) v = *(const float4*)(emb + (size_t)s_tok[b] * E_ + k);
            else        v = *(const float4*)(g_h + b * H_ + (k - E_));
            As[q * 4 + 0][b] = v.x; As[q * 4 + 1][b] = v.y;
            As[q * 4 + 2][b] = v.z; As[q * 4 + 3][b] = v.w;
        }
        #pragma unroll
        for (int u = 0; u < 2; u++) {
            int idx = tid * 2 + u;
            int rr = idx >> 3, q = idx & 7;
            int k = k0 + q * 4;
            int r = r0 + rr;
            float4 v;
            if (region == 0) {
                if (k < E_) v = *(const float4*)(W_ih + (size_t)r * E_ + k);
                else        v = *(const float4*)(W_hh + (size_t)r * H_ + (k - E_));
            } else if (region == 1) {
                v = *(const float4*)(W_ih + (size_t)r * E_ + k);
            } else {
                v = *(const float4*)(W_hh + (size_t)(r - 512) * H_ + (k - E_));
            }
            Bs[q * 4 + 0][rr] = v.x; Bs[q * 4 + 1][rr] = v.y;
            Bs[q * 4 + 2][rr] = v.z; Bs[q * 4 + 3][rr] = v.w;
        }
        __syncthreads();

        #pragma unroll
        for (int k = 0; k < 32; k++) {
            float a[4], w[4];
            *(float4*)a = *(const float4*)&As[k][ty * 4];
            *(float4*)w = *(const float4*)&Bs[k][tx * 4];
            #pragma unroll
            for (int i = 0; i < 4; i++)
                #pragma unroll
                for (int j = 0; j < 4; j++)
                    acc[i][j] = fmaf(a[i], w[j], acc[i][j]);
        }
    }

    float* outp = &g_part[ks][0];
    #pragma unroll
    for (int i = 0; i < 4; i++) {
        int b = ty * 4 + i;
        #pragma unroll
        for (int j = 0; j < 4; j++) {
            int r = r0 + tx * 4 + j;
            outp[b * GR_ + r] = acc[i][j];
        }
    }
}

// ---------------- gate nonlinearity + hidden update (in place) ----------------
__global__ __launch_bounds__(256) void k_gates_elem(
    const float* __restrict__ b_ih, const float* __restrict__ b_hh)
{
    int i = blockIdx.x * blockDim.x + threadIdx.x;
    if (i >= B_ * H_) return;
    int b = i >> 9;
    int j = i & 511;

    float sr = 0.f, sz = 0.f, in_ = 0.f, hn = 0.f;
    #pragma unroll
    for (int s = 0; s < KSPLIT_; s++) {
        const float* row = &g_part[s][b * GR_];
        sr  += row[j];
        sz  += row[512 + j];
        in_ += row[1024 + j];
        hn  += row[1536 + j];
    }
    sr  += b_ih[j] + b_hh[j];
    sz  += b_ih[512 + j] + b_hh[512 + j];
    in_ += b_ih[1024 + j];
    hn  += b_hh[1024 + j];

    float r = 1.f / (1.f + expf(-sr));
    float z = 1.f / (1.f + expf(-sz));
    float n = tanhf(in_ + r * hn);
    g_h[i] = (1.f - z) * n + z * g_h[i];
}

// ---------------- classifier logits + fused argmax (FFMA2, 64b x 128v tiles) ----------------
// Thread map (256 threads): tx = tid&15, ty = tid>>4.
//   batch rows  b = ty*4 + i   (i<4)   -> 64 rows
//   vocab cols  v = v0 + j*16 + tx (j<8) -> 128 cols
// smem: k-contiguous rows, stride 36 words (==4 mod 32 banks): B-loads by 16
// consecutive tx rows hit bank offsets tx*4 -> exactly the 2-wavefront minimum.
// Accumulators are f32x2 pairs over (even k, odd k); folded in the epilogue.
__global__ __launch_bounds__(256, 2) void k_logits(
    int t,
    const float* __restrict__ Wc,
    const float* __restrict__ bc,
    float* __restrict__ out)
{
    int v0 = blockIdx.x * 128;
    __shared__ float As[64][36];
    __shared__ float Bs[128][36];

    int tid = threadIdx.x;
    int tx = tid & 15, ty = tid >> 4;

    unsigned long long acc[4][8];
    #pragma unroll
    for (int i = 0; i < 4; i++)
        #pragma unroll
        for (int j = 0; j < 8; j++) acc[i][j] = 0ull;

    for (int kc = 0; kc < H_; kc += 32) {
        __syncthreads();
        // A tile: 64 rows x 32 k  (2 float4 per thread)
        #pragma unroll
        for (int u = 0; u < 2; u++) {
            int idx = tid + u * 256;
            int row = idx >> 3, c4 = idx & 7;
            float4 v = *(const float4*)(g_h + row * H_ + kc + c4 * 4);
            *(float4*)&As[row][c4 * 4] = v;
        }
        // B tile: 128 rows x 32 k (4 float4 per thread)
        #pragma unroll
        for (int u = 0; u < 4; u++) {
            int idx = tid + u * 256;
            int row = idx >> 3, c4 = idx & 7;
            int vg = v0 + row;
            float4 w;
            if (vg < V_) w = *(const float4*)(Wc + (size_t)vg * H_ + kc + c4 * 4);
            else         w = make_float4(0.f, 0.f, 0.f, 0.f);
            *(float4*)&Bs[row][c4 * 4] = w;
        }
        __syncthreads();

        #pragma unroll
        for (int kq = 0; kq < 32; kq += 4) {
            ulonglong2 a[4];
            #pragma unroll
            for (int i = 0; i < 4; i++)
                a[i] = *(const ulonglong2*)&As[ty * 4 + i][kq];
            #pragma unroll
            for (int jh = 0; jh < 2; jh++) {
                ulonglong2 w[4];
                #pragma unroll
                for (int jj = 0; jj < 4; jj++)
                    w[jj] = *(const ulonglong2*)&Bs[(jh * 4 + jj) * 16 + tx][kq];
                #pragma unroll
                for (int i = 0; i < 4; i++)
                    #pragma unroll
                    for (int jj = 0; jj < 4; jj++) {
                        int j = jh * 4 + jj;
                        acc[i][j] = ffma2(a[i].x, w[jj].x, acc[i][j]);
                        acc[i][j] = ffma2(a[i].y, w[jj].y, acc[i][j]);
                    }
            }
        }
    }

    // epilogue: fold pairs, add bias, store logits, packed-key argmax
    float* outt = out + (size_t)t * B_ * V_;
    unsigned long long best[4] = {0ull, 0ull, 0ull, 0ull};
    #pragma unroll
    for (int j = 0; j < 8; j++) {
        int vg = v0 + j * 16 + tx;
        if (vg >= V_) continue;
        float bcv = bc[vg];
        #pragma unroll
        for (int i = 0; i < 4; i++) {
            int b = ty * 4 + i;
            float lo = __uint_as_float((unsigned)(acc[i][j] & 0xFFFFFFFFull));
            float hi = __uint_as_float((unsigned)(acc[i][j] >> 32));
            float l = lo + hi + bcv;
            outt[(size_t)b * V_ + vg] = l;
            unsigned u = __float_as_uint(l);
            u = (u & 0x80000000u) ? ~u : (u | 0x80000000u);  // orderable float
            unsigned long long key =
                ((unsigned long long)u << 32) | (unsigned long long)(0xFFFFFFFFu - (unsigned)vg);
            if (key > best[i]) best[i] = key;                // ties -> lowest index
        }
    }
    // reduce across the 16 v-lanes (tx) sharing the same 4 batch rows
    #pragma unroll
    for (int off = 8; off > 0; off >>= 1) {
        #pragma unroll
        for (int i = 0; i < 4; i++) {
            unsigned long long o = __shfl_down_sync(0xFFFFFFFFu, best[i], off, 16);
            if (o > best[i]) best[i] = o;
        }
    }
    if (tx == 0) {
        #pragma unroll
        for (int i = 0; i < 4; i++)
            atomicMax(&g_amax[t][ty * 4 + i], best[i]);
    }
}

// ---------------- launch ----------------
extern "C" void kernel_launch(void* const* d_in, const int* in_sizes, int n_in,
                              void* d_out, int out_size) {
    const float* h0   = (const float*)d_in[0];
    const float* emb  = (const float*)d_in[1];
    const float* W_ih = (const float*)d_in[2];
    const float* W_hh = (const float*)d_in[3];
    const float* b_ih = (const float*)d_in[4];
    const float* b_hh = (const float*)d_in[5];
    const float* Wc   = (const float*)d_in[6];
    const float* bc   = (const float*)d_in[7];
    float* out = (float*)d_out;

    k_init<<<32, 256>>>(h0);
    int gemm_blocks   = (GR_ / 64) * KSPLIT_;       // 128
    int elem_blocks   = (B_ * H_) / 256;            // 128
    int logits_blocks = (V_ + 127) / 128;           // 393
    for (int t = 0; t < L_; t++) {
        k_gates_gemm<<<gemm_blocks, 256>>>(t, emb, W_ih, W_hh);
        k_gates_elem<<<elem_blocks, 256>>>(b_ih, b_hh);
        k_logits<<<logits_blocks, 256>>>(t, Wc, bc, out);
    }
}

// round 7
// speedup vs baseline: 1.3438x; 1.1407x over previous
#include <cuda_runtime.h>
#include <math.h>

// Problem constants
#define V_  50257
#define E_  256
#define H_  512
#define B_  64
#define L_  64
#define SOS_ 2

#define GR_     2048
#define KSPLIT_ 4
#define KTOT_   768
#define KPER_   (KTOT_ / KSPLIT_)   // 192

// logits tiling
#define VT_   176                   // v-tile per block
#define NJ_   11                    // VT_/16
#define AW_   2304                  // A stage words: 64*36
#define BW_   5632                  // B stage words: 176*32
#define SMEMW_ (2*AW_ + 2*BW_)      // 15872 words = 63488 bytes

// ---------------- device scratch ----------------
__device__ float g_h[B_ * H_];
__device__ float g_part[KSPLIT_][B_ * GR_];
__device__ unsigned long long g_amax[L_][B_];

__device__ __forceinline__ unsigned long long ffma2(
    unsigned long long a, unsigned long long b, unsigned long long c)
{
    unsigned long long d;
    asm("fma.rn.f32x2 %0, %1, %2, %3;" : "=l"(d) : "l"(a), "l"(b), "l"(c));
    return d;
}

__device__ __forceinline__ void cp_async16(unsigned dst, const float* src) {
    asm volatile("cp.async.cg.shared.global [%0], [%1], 16;" :: "r"(dst), "l"(src));
}
__device__ __forceinline__ void cp_async8(unsigned dst, const float* src, int bytes) {
    asm volatile("cp.async.ca.shared.global [%0], [%1], 8, %2;"
                 :: "r"(dst), "l"(src), "r"(bytes));
}

// ---------------- init ----------------
__global__ void k_init(const float* __restrict__ h0) {
    int stride = gridDim.x * blockDim.x;
    int i = blockIdx.x * blockDim.x + threadIdx.x;
    for (int j = i; j < B_ * H_; j += stride) g_h[j] = h0[j];
    unsigned long long* am = &g_amax[0][0];
    for (int j = i; j < L_ * B_; j += stride) am[j] = 0ull;
}

// ---------------- gate GEMM (unchanged, verified) ----------------
__global__ __launch_bounds__(256) void k_gates_gemm(
    int t,
    const float* __restrict__ emb,
    const float* __restrict__ W_ih,
    const float* __restrict__ W_hh)
{
    int rt = blockIdx.x / KSPLIT_;
    int ks = blockIdx.x % KSPLIT_;
    int r0 = rt * 64;
    int kbase = ks * KPER_;
    int region = (r0 < 1024) ? 0 : (r0 < 1536 ? 1 : 2);

    __shared__ float As[32][68];
    __shared__ float Bs[32][68];
    __shared__ int   s_tok[B_];

    int tid = threadIdx.x;
    if (tid < B_) {
        int tok;
        if (t == 0) tok = SOS_;
        else {
            unsigned long long key = g_amax[t - 1][tid];
            tok = (int)(0xFFFFFFFFu - (unsigned)(key & 0xFFFFFFFFull));
        }
        s_tok[tid] = tok;
    }
    __syncthreads();

    int tx = tid & 15, ty = tid >> 4;
    float acc[4][4] = {};

    for (int kc = 0; kc < KPER_; kc += 32) {
        int k0 = kbase + kc;
        if (region == 1 && k0 >= E_) continue;
        if (region == 2 && k0 + 32 <= E_) continue;

        __syncthreads();
        #pragma unroll
        for (int u = 0; u < 2; u++) {
            int idx = tid * 2 + u;
            int b = idx >> 3, q = idx & 7;
            int k = k0 + q * 4;
            float4 v;
            if (k < E_) v = *(const float4*)(emb + (size_t)s_tok[b] * E_ + k);
            else        v = *(const float4*)(g_h + b * H_ + (k - E_));
            As[q * 4 + 0][b] = v.x; As[q * 4 + 1][b] = v.y;
            As[q * 4 + 2][b] = v.z; As[q * 4 + 3][b] = v.w;
        }
        #pragma unroll
        for (int u = 0; u < 2; u++) {
            int idx = tid * 2 + u;
            int rr = idx >> 3, q = idx & 7;
            int k = k0 + q * 4;
            int r = r0 + rr;
            float4 v;
            if (region == 0) {
                if (k < E_) v = *(const float4*)(W_ih + (size_t)r * E_ + k);
                else        v = *(const float4*)(W_hh + (size_t)r * H_ + (k - E_));
            } else if (region == 1) {
                v = *(const float4*)(W_ih + (size_t)r * E_ + k);
            } else {
                v = *(const float4*)(W_hh + (size_t)(r - 512) * H_ + (k - E_));
            }
            Bs[q * 4 + 0][rr] = v.x; Bs[q * 4 + 1][rr] = v.y;
            Bs[q * 4 + 2][rr] = v.z; Bs[q * 4 + 3][rr] = v.w;
        }
        __syncthreads();

        #pragma unroll
        for (int k = 0; k < 32; k++) {
            float a[4], w[4];
            *(float4*)a = *(const float4*)&As[k][ty * 4];
            *(float4*)w = *(const float4*)&Bs[k][tx * 4];
            #pragma unroll
            for (int i = 0; i < 4; i++)
                #pragma unroll
                for (int j = 0; j < 4; j++)
                    acc[i][j] = fmaf(a[i], w[j], acc[i][j]);
        }
    }

    float* outp = &g_part[ks][0];
    #pragma unroll
    for (int i = 0; i < 4; i++) {
        int b = ty * 4 + i;
        #pragma unroll
        for (int j = 0; j < 4; j++) {
            int r = r0 + tx * 4 + j;
            outp[b * GR_ + r] = acc[i][j];
        }
    }
}

// ---------------- gate nonlinearity + hidden update ----------------
__global__ __launch_bounds__(256) void k_gates_elem(
    const float* __restrict__ b_ih, const float* __restrict__ b_hh)
{
    int i = blockIdx.x * blockDim.x + threadIdx.x;
    if (i >= B_ * H_) return;
    int b = i >> 9;
    int j = i & 511;

    float sr = 0.f, sz = 0.f, in_ = 0.f, hn = 0.f;
    #pragma unroll
    for (int s = 0; s < KSPLIT_; s++) {
        const float* row = &g_part[s][b * GR_];
        sr  += row[j];
        sz  += row[512 + j];
        in_ += row[1024 + j];
        hn  += row[1536 + j];
    }
    sr  += b_ih[j] + b_hh[j];
    sz  += b_ih[512 + j] + b_hh[512 + j];
    in_ += b_ih[1024 + j];
    hn  += b_hh[1024 + j];

    float r = 1.f / (1.f + expf(-sr));
    float z = 1.f / (1.f + expf(-sz));
    float n = tanhf(in_ + r * hn);
    g_h[i] = (1.f - z) * n + z * g_h[i];
}

// ---------------- classifier logits + fused argmax ----------------
// 64b x 176v tiles, grid=286 (single wave at occ 2), FFMA2 accumulators,
// cp.async double-buffered stages, XOR-swizzled B tile (conflict-free LDS.64).
// smem (dynamic, words): [A stage0 | A stage1 | B stage0 | B stage1]
//   A stage: 64 rows x 36 (padded, k-contiguous)
//   B stage: 176 rows x 32, word idx = k ^ (2*(row&15))  (8B-granular swizzle)
__global__ __launch_bounds__(256, 2) void k_logits(
    int t,
    const float* __restrict__ Wc,
    const float* __restrict__ bc,
    float* __restrict__ out)
{
    extern __shared__ float sm[];
    int v0 = blockIdx.x * VT_;
    int tid = threadIdx.x;
    int tx = tid & 15, ty = tid >> 4;

    unsigned smem_u32 = (unsigned)__cvta_generic_to_shared(sm);

    unsigned long long acc[4][NJ_];
    #pragma unroll
    for (int i = 0; i < 4; i++)
        #pragma unroll
        for (int j = 0; j < NJ_; j++) acc[i][j] = 0ull;

    // ---- stage loader: A (16B cp.async) + B (8B cp.async, swizzled) ----
    auto load_stage = [&](int st, int kc) {
        // A: 64 rows x 32 k = 512 float4; 2 per thread
        #pragma unroll
        for (int u = 0; u < 2; u++) {
            int idx = tid + u * 256;
            int row = idx >> 3, c4 = idx & 7;
            unsigned dst = smem_u32 + ((st * AW_ + row * 36 + c4 * 4) << 2);
            cp_async16(dst, g_h + row * H_ + kc + c4 * 4);
        }
        // B: 176 rows x 16 k-pairs = 2816 8B chunks; 11 per thread
        #pragma unroll
        for (int u = 0; u < 11; u++) {
            int idx = tid + u * 256;
            int row = idx >> 4, p = idx & 15;
            int vg = v0 + row;
            int sw = (2 * p) ^ (2 * (row & 15));
            unsigned dst = smem_u32 + ((2 * AW_ + st * BW_ + row * 32 + sw) << 2);
            const float* src = (vg < V_) ? (Wc + (size_t)vg * H_ + kc + 2 * p) : Wc;
            cp_async8(dst, src, (vg < V_) ? 8 : 0);
        }
    };

    load_stage(0, 0);
    asm volatile("cp.async.commit_group;");

    #pragma unroll 1
    for (int s = 0; s < 16; s++) {
        if (s < 15) {
            load_stage((s + 1) & 1, (s + 1) * 32);
            asm volatile("cp.async.commit_group;");
            asm volatile("cp.async.wait_group 1;");
        } else {
            asm volatile("cp.async.wait_group 0;");
        }
        __syncthreads();

        const float* A = sm + (s & 1) * AW_;
        const float* B = sm + 2 * AW_ + (s & 1) * BW_;
        int xr = 2 * tx;   // swizzle term: row&15 == tx for row = j*16+tx

        #pragma unroll
        for (int kq = 0; kq < 32; kq += 2) {
            unsigned long long a0 = *(const unsigned long long*)(A + (ty * 4 + 0) * 36 + kq);
            unsigned long long a1 = *(const unsigned long long*)(A + (ty * 4 + 1) * 36 + kq);
            unsigned long long a2 = *(const unsigned long long*)(A + (ty * 4 + 2) * 36 + kq);
            unsigned long long a3 = *(const unsigned long long*)(A + (ty * 4 + 3) * 36 + kq);
            int ksw = kq ^ xr;
            #pragma unroll
            for (int j = 0; j < NJ_; j++) {
                unsigned long long w =
                    *(const unsigned long long*)(B + (j * 16 + tx) * 32 + ksw);
                acc[0][j] = ffma2(a0, w, acc[0][j]);
                acc[1][j] = ffma2(a1, w, acc[1][j]);
                acc[2][j] = ffma2(a2, w, acc[2][j]);
                acc[3][j] = ffma2(a3, w, acc[3][j]);
            }
        }
        __syncthreads();
    }

    // ---- epilogue: fold pairs, bias, store, packed-key argmax ----
    float* outt = out + (size_t)t * B_ * V_;
    unsigned long long best[4] = {0ull, 0ull, 0ull, 0ull};
    #pragma unroll
    for (int j = 0; j < NJ_; j++) {
        int vg = v0 + j * 16 + tx;
        if (vg >= V_) continue;
        float bcv = bc[vg];
        #pragma unroll
        for (int i = 0; i < 4; i++) {
            int b = ty * 4 + i;
            float lo = __uint_as_float((unsigned)(acc[i][j] & 0xFFFFFFFFull));
            float hi = __uint_as_float((unsigned)(acc[i][j] >> 32));
            float l = lo + hi + bcv;
            outt[(size_t)b * V_ + vg] = l;
            unsigned u = __float_as_uint(l);
            u = (u & 0x80000000u) ? ~u : (u | 0x80000000u);
            unsigned long long key =
                ((unsigned long long)u << 32) | (unsigned long long)(0xFFFFFFFFu - (unsigned)vg);
            if (key > best[i]) best[i] = key;
        }
    }
    #pragma unroll
    for (int off = 8; off > 0; off >>= 1) {
        #pragma unroll
        for (int i = 0; i < 4; i++) {
            unsigned long long o = __shfl_down_sync(0xFFFFFFFFu, best[i], off, 16);
            if (o > best[i]) best[i] = o;
        }
    }
    if (tx == 0) {
        #pragma unroll
        for (int i = 0; i < 4; i++)
            atomicMax(&g_amax[t][ty * 4 + i], best[i]);
    }
}

// ---------------- launch ----------------
extern "C" void kernel_launch(void* const* d_in, const int* in_sizes, int n_in,
                              void* d_out, int out_size) {
    const float* h0   = (const float*)d_in[0];
    const float* emb  = (const float*)d_in[1];
    const float* W_ih = (const float*)d_in[2];
    const float* W_hh = (const float*)d_in[3];
    const float* b_ih = (const float*)d_in[4];
    const float* b_hh = (const float*)d_in[5];
    const float* Wc   = (const float*)d_in[6];
    const float* bc   = (const float*)d_in[7];
    float* out = (float*)d_out;

    cudaFuncSetAttribute(k_logits, cudaFuncAttributeMaxDynamicSharedMemorySize,
                         SMEMW_ * 4);

    k_init<<<32, 256>>>(h0);
    int gemm_blocks   = (GR_ / 64) * KSPLIT_;       // 128
    int elem_blocks   = (B_ * H_) / 256;            // 128
    int logits_blocks = (V_ + VT_ - 1) / VT_;       // 286
    for (int t = 0; t < L_; t++) {
        k_gates_gemm<<<gemm_blocks, 256>>>(t, emb, W_ih, W_hh);
        k_gates_elem<<<elem_blocks, 256>>>(b_ih, b_hh);
        k_logits<<<logits_blocks, 256, SMEMW_ * 4>>>(t, Wc, bc, out);
    }
}